// round 12
// baseline (speedup 1.0000x reference)
#include <cuda_runtime.h>
#include <math.h>

// ---------------- static problem constants ----------------
#define BGR 4
#define NN  40962
#define DEG 6
#define E0C (BGR * NN * DEG)          // 983052
#define M0  (BGR * NN)                // 163848
#define NB  148                        // persistent blocks (1/SM, GB300 has 152 SMs)
#define NT  1024
#define GS  (NB * NT)
#define NWP (GS / 32)

// ---------------- device scratch (static, no allocation) ----------------
__device__ __align__(128) float    g_H  [5243392];
__device__ __align__(128) float    g_XB [5243392];
__device__ __align__(128) float    g_XA [2621952];
__device__ float    g_deg[M0];
__device__ float    g_score[M0];
__device__ unsigned g_key[M0];
__device__ int      g_remap[M0];
__device__ int      g_srcbuf[2 * E0C];
__device__ int      g_dstbuf[2 * E0C];
__device__ int      g_ecnt[2];
__device__ unsigned g_hist12[BGR * 4096];
__device__ unsigned g_thresh[BGR];
__device__ int      g_allow[BGR];
__device__ int      g_cntK[BGR];
__device__ int      g_cntE[BGR];
__device__ float    g_pinv[4];
__device__ float    g_pmax[128 * 128];
__device__ float    g_psum[128 * 128];
__device__ unsigned g_barCnt;          // reset via cudaMemsetAsync before each launch

// ---------------- helpers ----------------
__device__ __forceinline__ unsigned long long pack2(float a, float b) {
    unsigned long long r;
    asm("mov.b64 %0,{%1,%2};" : "=l"(r) : "f"(a), "f"(b));
    return r;
}
__device__ __forceinline__ void unpack2(unsigned long long v, float& a, float& b) {
    asm("mov.b64 {%0,%1},%2;" : "=f"(a), "=f"(b) : "l"(v));
}
__device__ __forceinline__ void ffma2(unsigned long long& acc, unsigned long long x,
                                      unsigned long long w) {
    asm("fma.rn.f32x2 %0,%1,%2,%0;" : "+l"(acc) : "l"(x), "l"(w));
}
__device__ __forceinline__ void red4(float* p, float4 v) {
    asm volatile("red.global.add.v4.f32 [%0],{%1,%2,%3,%4};"
                 :: "l"(p), "f"(v.x), "f"(v.y), "f"(v.z), "f"(v.w) : "memory");
}

// software grid barrier: release-arrive + acquire-spin + gpu-scope fence
// (membar.gl -> CCTL.IVALL: invalidates this SM's L1 so post-barrier plain
// loads observe other SMs' writes). All NB blocks resident (1/SM) => no deadlock.
__device__ __forceinline__ void gridbar(unsigned& gen) {
    gen += NB;
    __syncthreads();
    if (threadIdx.x == 0) {
        __threadfence();   // release: flush this SM's prior writes
        asm volatile("red.release.gpu.global.add.u32 [%0], 1;"
                     :: "l"(&g_barCnt) : "memory");
        unsigned v;
        do {
            asm volatile("ld.acquire.gpu.global.u32 %0, [%1];"
                         : "=r"(v) : "l"(&g_barCnt) : "memory");
        } while (v < gen);
        __threadfence();   // acquire: invalidate L1 for fresh loads
    }
    __syncthreads();
}

// ---------------- stage bodies (grid-stride; math identical to prior rounds) ----------------
template <int FI, int FO>
__device__ void mm_stage(float* sX, const float* __restrict__ X,
                         const float* __restrict__ W, int M) {
    constexpr int J = FO / 4;
    constexpr int G = NT / J;
    int ngrp = (M + G - 1) / G;
    for (int grp = blockIdx.x; grp < ngrp; grp += NB) {
        int r0 = grp * G;
        __syncthreads();
        for (int idx = threadIdx.x; idx < G * FI; idx += NT) {
            int r = r0 + idx / FI;
            sX[idx] = (r < M) ? X[(size_t)r * FI + (idx % FI)] : 0.f;
        }
        __syncthreads();
        int g = threadIdx.x / J, j = (threadIdx.x % J) * 4;
        int m = r0 + g;
        if (m < M) {
            const float* xr = sX + g * FI;
            unsigned long long a0 = 0ull, a1 = 0ull;
#pragma unroll
            for (int kq = 0; kq < FI; kq++) {
                float xv = xr[kq];
                unsigned long long xx = pack2(xv, xv);
                ulonglong2 wv = *(const ulonglong2*)(W + kq * FO + j);
                ffma2(a0, xx, wv.x);
                ffma2(a1, xx, wv.y);
            }
            float v0, v1, v2, v3;
            unpack2(a0, v0, v1);
            unpack2(a1, v2, v3);
            float dv = rsqrtf(g_deg[m] + 1.0f);
            float4 hv = make_float4(v0 * dv, v1 * dv, v2 * dv, v3 * dv);
            *(float4*)(g_H  + (size_t)m * FO + j) = hv;
            *(float4*)(g_XB + (size_t)m * FO + j) = hv;
        }
    }
}

template <int FO>
__device__ void agg_stage(const int* __restrict__ src, const int* __restrict__ dst, int E) {
    constexpr int LC = (FO == 32) ? 3 : (FO == 64) ? 4 : 5;
    constexpr int CM = (1 << LC) - 1;
    int total = E << LC;
    int t = blockIdx.x * NT + threadIdx.x;
    for (int i = t; i < total; i += GS) {
        int e = i >> LC, c = i & CM;
        int s = src[e], d = dst[e];
        float4 h = *(const float4*)(g_H + (size_t)s * FO + c * 4);
        red4(g_XB + (size_t)d * FO + c * 4, h);
    }
}

template <int FO>
__device__ void score_stage(const float* __restrict__ bias, const float* __restrict__ p,
                            int M, int n) {
    int gw = (blockIdx.x * NT + threadIdx.x) >> 5;
    int lane = threadIdx.x & 31;
    for (int m = gw; m < M; m += NWP) {
        float dv = rsqrtf(g_deg[m] + 1.0f);
        float acc = 0.f;
#pragma unroll
        for (int f = lane; f < FO; f += 32) {
            float v = g_XB[(size_t)m * FO + f] * dv + bias[f];
            acc += fmaxf(v, 0.f) * p[f];
        }
#pragma unroll
        for (int o = 16; o; o >>= 1) acc += __shfl_down_sync(0xffffffffu, acc, o);
        if (lane == 0) {
            g_score[m] = acc;
            unsigned u = __float_as_uint(acc);
            unsigned kk = (u & 0x80000000u) ? ~u : (u | 0x80000000u);
            g_key[m] = kk;
            atomicAdd(&g_hist12[(m / n) * 4096 + (kk >> 20)], 1u);
        }
    }
}

__device__ void select_stage(unsigned* sh, unsigned* arr, unsigned* sPfx, int* sW,
                             int n, int k, int MN, int* eCn) {
    int b = blockIdx.x, t = threadIdx.x;
    if (b >= BGR) return;
    const unsigned* kb = g_key + b * n;
    unsigned* hb = g_hist12 + b * 4096;

    // phase 1: top 12 bits (bins precomputed by score); re-zero bins
    for (int i = t; i < 4096; i += NT) { sh[i] = hb[i]; hb[i] = 0u; }
    __syncthreads();
    {
        unsigned s = sh[t * 4] + sh[t * 4 + 1] + sh[t * 4 + 2] + sh[t * 4 + 3];
        arr[t] = s;
        __syncthreads();
        for (int off = 1; off < 1024; off <<= 1) {
            unsigned v = (t + off < 1024) ? arr[t + off] : 0u;
            __syncthreads();
            arr[t] += v;
            __syncthreads();
        }
        unsigned above = arr[t] - s;
        if (above < (unsigned)k && above + s >= (unsigned)k) {
            unsigned cum = above;
            for (int j = 3; j >= 0; j--) {
                unsigned h = sh[t * 4 + j];
                if (cum + h >= (unsigned)k) { *sPfx = t * 4 + j; *sW = k - (int)cum; break; }
                cum += h;
            }
        }
    }
    __syncthreads();
    unsigned pfx1 = *sPfx;
    int want = *sW;

    // phase 2: bits [19:8]
    __syncthreads();
    for (int i = t; i < 4096; i += NT) sh[i] = 0u;
    __syncthreads();
    for (int i = t; i < n; i += NT) {
        unsigned kk = kb[i];
        if ((kk >> 20) == pfx1) atomicAdd(&sh[(kk >> 8) & 0xFFFu], 1u);
    }
    __syncthreads();
    {
        unsigned s = sh[t * 4] + sh[t * 4 + 1] + sh[t * 4 + 2] + sh[t * 4 + 3];
        arr[t] = s;
        __syncthreads();
        for (int off = 1; off < 1024; off <<= 1) {
            unsigned v = (t + off < 1024) ? arr[t + off] : 0u;
            __syncthreads();
            arr[t] += v;
            __syncthreads();
        }
        unsigned above = arr[t] - s;
        if (above < (unsigned)want && above + s >= (unsigned)want) {
            unsigned cum = above;
            for (int j = 3; j >= 0; j--) {
                unsigned h = sh[t * 4 + j];
                if (cum + h >= (unsigned)want) { *sPfx = t * 4 + j; *sW = want - (int)cum; break; }
                cum += h;
            }
        }
    }
    __syncthreads();
    unsigned pfx2 = *sPfx;
    want = *sW;
    unsigned pfx24 = (pfx1 << 12) | pfx2;

    // phase 3: final byte
    __syncthreads();
    if (t < 256) sh[t] = 0u;
    __syncthreads();
    for (int i = t; i < n; i += NT) {
        unsigned kk = kb[i];
        if ((kk >> 8) == pfx24) atomicAdd(&sh[kk & 0xFFu], 1u);
    }
    __syncthreads();
    if (t == 0) {
        unsigned cum = 0;
        int d = 255;
        for (;;) {
            unsigned h = sh[d];
            if (cum + h >= (unsigned)want || d == 0) break;
            cum += h;
            d--;
        }
        g_thresh[b] = (pfx24 << 8) | (unsigned)d;
        g_allow[b] = want - (int)cum;
        g_cntK[b] = 0;
        g_cntE[b] = 0;
        if (b == 0) *eCn = 0;
    }
    for (int i = b * NT + t; i < MN; i += BGR * NT) g_deg[i] = 0.f;
}

template <int FO>
__device__ void cg_stage(const float* __restrict__ bias, int pidx, int M, int n, int k) {
    int lane = threadIdx.x & 31;
    int gw = (blockIdx.x * NT + threadIdx.x) >> 5;
    float pv = g_pinv[pidx];
    constexpr int LPR = FO / 4;
    constexpr int RPI = 32 / LPR;
    int sub = lane / LPR;
    int chunk = lane % LPR;
    float4 bv = *(const float4*)(bias + chunk * 4);
    for (int base = gw * 32; base < M; base += NWP * 32) {
        int m = base + lane;
        bool active = (m < M);
        int b = 0;
        bool keep = false;
        if (active) {
            b = m / n;
            unsigned kk = g_key[m], th = g_thresh[b];
            keep = kk > th;
            if (!keep && kk == th)
                keep = (atomicAdd(&g_cntE[b], 1) < g_allow[b]);
        }
        int nid = -1;
        bool uniformWarp = (base + 31 < M) && ((base / n) == ((base + 31) / n));
        if (uniformWarp) {
            unsigned km = __ballot_sync(0xffffffffu, keep);
            int leader = __ffs(km) - 1;
            int bp = 0;
            if (keep && lane == leader) bp = atomicAdd(&g_cntK[b], __popc(km));
            bp = __shfl_sync(0xffffffffu, bp, (leader < 0) ? 0 : leader);
            if (keep) nid = b * k + bp + __popc(km & ((1u << lane) - 1u));
        } else {
            if (keep) nid = b * k + atomicAdd(&g_cntK[b], 1);
        }
        if (active) g_remap[m] = nid;

        float dvm = active ? rsqrtf(g_deg[m] + 1.0f) : 0.f;
        float tv = keep ? tanhf(g_score[m] * pv) : 0.f;
        unsigned fk = __ballot_sync(0xffffffffu, keep);
        int cnt = __popc(fk);
#pragma unroll 1
        for (int g = 0; g < cnt; g += RPI) {
            int slot = g + sub;
            int r = (slot < cnt) ? (int)__fns(fk, 0, slot + 1) : 0;
            int nid_r = __shfl_sync(0xffffffffu, nid, r);
            float t_r  = __shfl_sync(0xffffffffu, tv, r);
            float dv_r = __shfl_sync(0xffffffffu, dvm, r);
            if (slot < cnt) {
                int m_r = base + r;
                float4 v = *(const float4*)(g_XB + (size_t)m_r * FO + chunk * 4);
                v.x = fmaxf(v.x * dv_r + bv.x, 0.f) * t_r;
                v.y = fmaxf(v.y * dv_r + bv.y, 0.f) * t_r;
                v.z = fmaxf(v.z * dv_r + bv.z, 0.f) * t_r;
                v.w = fmaxf(v.w * dv_r + bv.w, 0.f) * t_r;
                *(float4*)(g_XA + (size_t)nid_r * FO + chunk * 4) = v;
            }
        }
    }
}

__device__ void eremap_stage(const int* __restrict__ srcO, const int* __restrict__ dstO,
                             int E, int* srcN, int* dstN, int* eCn) {
    int gt = blockIdx.x * NT + threadIdx.x;
    int lane = threadIdx.x & 31;
    for (int e = gt; __any_sync(0xffffffffu, e < E); e += GS) {
        bool in = (e < E);
        int s = -1, d = -1;
        if (in) {
            s = g_remap[srcO[e]];
            d = g_remap[dstO[e]];
        }
        bool valid = in && (s >= 0) && (d >= 0);
        unsigned mask = __ballot_sync(0xffffffffu, valid);
        if (!mask) continue;
        int leader = __ffs(mask) - 1;
        int bp = 0;
        if (lane == leader) bp = atomicAdd(eCn, __popc(mask));
        bp = __shfl_sync(0xffffffffu, bp, leader);
        if (valid) {
            int pos = bp + __popc(mask & ((1u << lane) - 1u));
            srcN[pos] = s;
            dstN[pos] = d;
            atomicAdd(&g_deg[d], 1.f);
        }
    }
}

template <int FI, int FO>
__device__ void layer_stage(unsigned& gen, float* shf, unsigned* shu, unsigned* sarr,
                            unsigned* sPfx, int* sW,
                            const float* Xin, const float* Wt, const float* bias,
                            const float* p, int pidx, int n, int k, int MN,
                            const int* eS, const int* eD, int E,
                            int* eSn, int* eDn, int* eCn, bool doRemap) {
    int M = BGR * n;
    mm_stage<FI, FO>(shf, Xin, Wt, M);
    gridbar(gen);
    agg_stage<FO>(eS, eD, E);
    gridbar(gen);
    score_stage<FO>(bias, p, M, n);
    gridbar(gen);
    select_stage(shu, sarr, sPfx, sW, n, k, MN, eCn);
    gridbar(gen);
    cg_stage<FO>(bias, pidx, M, n, k);
    gridbar(gen);
    if (doRemap) {
        eremap_stage(eS, eD, E, eSn, eDn, eCn);
        gridbar(gen);
    }
}

// ---------------- the megakernel ----------------
__global__ void __launch_bounds__(NT)
k_mega(const float* __restrict__ x0, const int* __restrict__ ei,
       const float* __restrict__ meta,
       const float* W1, const float* b1, const float* p1,
       const float* W2, const float* b2, const float* p2,
       const float* W3, const float* b3, const float* p3,
       const float* W4, const float* b4, const float* p4,
       const float* cw, const float* cb, const float* fcw, const float* fcb,
       const float* fc2w, const float* fc2b, float* out) {
    __shared__ unsigned s_hist[4096];
    __shared__ unsigned s_arr[1024];
    __shared__ unsigned s_pfx;
    __shared__ int s_w;
    float* shf = (float*)s_hist;   // mm tile / read2 buffers alias select hist

    unsigned gen = 0;
    int gt = blockIdx.x * NT + threadIdx.x;

    // stage 0: zero deg + hist12, compute pinv
    for (int i = gt; i < M0; i += GS) g_deg[i] = 0.f;
    for (int i = gt; i < BGR * 4096; i += GS) g_hist12[i] = 0u;
    if (blockIdx.x < 4 && threadIdx.x < 32) {
        const float* p = (blockIdx.x == 0) ? p1 : (blockIdx.x == 1) ? p2
                         : (blockIdx.x == 2) ? p3 : p4;
        int len = (blockIdx.x == 0) ? 32 : (blockIdx.x == 1) ? 64 : 128;
        float acc = 0.f;
        for (int f = threadIdx.x; f < len; f += 32) { float v = p[f]; acc += v * v; }
#pragma unroll
        for (int o = 16; o; o >>= 1) acc += __shfl_down_sync(0xffffffffu, acc, o);
        if (threadIdx.x == 0) g_pinv[blockIdx.x] = rsqrtf(acc);
    }
    gridbar(gen);

    // stage 1: layer-0 degree count
    {
        const int* dst0 = ei + E0C;
        for (int e = gt; e < E0C; e += GS) atomicAdd(&g_deg[dst0[e]], 1.0f);
    }
    gridbar(gen);

    // layers (edge-buffer ping-pong identical to prior rounds)
    layer_stage<4, 32>(gen, shf, s_hist, s_arr, &s_pfx, &s_w,
                       x0, W1, b1, p1, 0, 40962, 20481, BGR * 20481,
                       ei, ei + E0C, E0C,
                       g_srcbuf, g_dstbuf, &g_ecnt[0], true);
    {
        int E = g_ecnt[0];
        layer_stage<32, 64>(gen, shf, s_hist, s_arr, &s_pfx, &s_w,
                            g_XA, W2, b2, p2, 1, 20481, 10241, BGR * 10241,
                            g_srcbuf, g_dstbuf, E,
                            g_srcbuf + E0C, g_dstbuf + E0C, &g_ecnt[1], true);
    }
    {
        int E = g_ecnt[1];
        layer_stage<64, 128>(gen, shf, s_hist, s_arr, &s_pfx, &s_w,
                             g_XA, W3, b3, p3, 2, 10241, 5121, BGR * 5121,
                             g_srcbuf + E0C, g_dstbuf + E0C, E,
                             g_srcbuf, g_dstbuf, &g_ecnt[0], true);
    }
    {
        int E = g_ecnt[0];
        layer_stage<128, 128>(gen, shf, s_hist, s_arr, &s_pfx, &s_w,
                              g_XA, W4, b4, p4, 3, 5121, 2561, 0,
                              g_srcbuf, g_dstbuf, E,
                              g_srcbuf + E0C, g_dstbuf + E0C, &g_ecnt[1], false);
    }

    // readout part 1: 128 slices (32 per graph)
    if (blockIdx.x < 128 && threadIdx.x < 128) {
        int slice = blockIdx.x;
        int b = slice >> 5, s = slice & 31, f = threadIdx.x;
        const int kn = 2561;
        int per = (kn + 31) / 32;
        int i0 = s * per, i1 = min(kn, i0 + per);
        float mx = -3.4e38f, sm = 0.f;
        const float* base = g_XA + (size_t)b * kn * 128 + f;
        for (int i = i0; i < i1; i++) {
            float v = base[(size_t)i * 128];
            mx = fmaxf(mx, v);
            sm += v;
        }
        g_pmax[slice * 128 + f] = mx;
        g_psum[slice * 128 + f] = sm;
    }
    gridbar(gen);

    // readout part 2
    if (blockIdx.x < 4) {
        float* v = shf;
        float* red = shf + 260;
        int b = blockIdx.x, f = threadIdx.x;
        if (f < 128) {
            float mx = -3.4e38f, sm = 0.f;
            for (int s = 0; s < 32; s++) {
                mx = fmaxf(mx, g_pmax[(b * 32 + s) * 128 + f]);
                sm += g_psum[(b * 32 + s) * 128 + f];
            }
            v[f] = mx;
            v[128 + f] = sm / 2561.f;
            if (f < 4) {
                float mv = meta[b] * cw[f] + cb[f];
                v[256 + f] = mv > 0.f ? mv : 0.f;
            }
        }
        __syncthreads();
        if (f < 128) {
            float acc = fcb[f];
            for (int i = 0; i < 260; i++) acc += v[i] * fcw[i * 128 + f];
            float hv = acc > 0.f ? acc : 0.f;
            red[f] = hv * fc2w[f];
        }
        __syncthreads();
        for (int s = 64; s > 0; s >>= 1) {
            if (f < s) red[f] += red[f + s];
            __syncthreads();
        }
        if (f == 0) out[b] = red[0] + fc2b[0];
    }
}

// ---------------- host orchestration ----------------
extern "C" void kernel_launch(void* const* d_in, const int* in_sizes, int n_in,
                              void* d_out, int out_size) {
    const float* x0   = (const float*)d_in[0];
    const int*   ei   = (const int*)  d_in[1];
    const float* meta = (const float*)d_in[2];
    const float* W1 = (const float*)d_in[3],  *b1 = (const float*)d_in[4],  *p1 = (const float*)d_in[5];
    const float* W2 = (const float*)d_in[6],  *b2 = (const float*)d_in[7],  *p2 = (const float*)d_in[8];
    const float* W3 = (const float*)d_in[9],  *b3 = (const float*)d_in[10], *p3 = (const float*)d_in[11];
    const float* W4 = (const float*)d_in[12], *b4 = (const float*)d_in[13], *p4 = (const float*)d_in[14];
    const float* cw   = (const float*)d_in[15];
    const float* cb   = (const float*)d_in[16];
    const float* fcw  = (const float*)d_in[17];
    const float* fcb  = (const float*)d_in[18];
    const float* fc2w = (const float*)d_in[19];
    const float* fc2b = (const float*)d_in[20];
    float* out = (float*)d_out;

    void* barPtr;
    cudaGetSymbolAddress(&barPtr, g_barCnt);
    cudaMemsetAsync(barPtr, 0, sizeof(unsigned), 0);   // reset barrier each replay

    k_mega<<<NB, NT>>>(x0, ei, meta, W1, b1, p1, W2, b2, p2, W3, b3, p3,
                       W4, b4, p4, cw, cb, fcw, fcb, fc2w, fc2b, out);
    (void)in_sizes; (void)n_in; (void)out_size;
}